// round 8
// baseline (speedup 1.0000x reference)
#include <cuda_runtime.h>
#include <cuda_bf16.h>

#define DD 128
#define HH 512
#define WW 512
#define THRESH 0.997f
#define KPK 131072
#define NB  65536                 // value buckets AND spatial cells (16*64*64)
#define NCH 64                    // scan chunks of 1024 buckets
#define CSLOTS 16                 // per-cell candidate capacity (lambda~1.5, safe)
#define NSLOT (NB*CSLOTS)         // 1,048,576

// ---------------- device scratch (static; all counters self-restore to 0) ------
__device__ unsigned c_cnt[NB];               // per-cell candidate count (zeroed by bucket_sort)
__device__ uint2    c_data[NSLOT];           // (idx, valbits) per cell slot
__device__ unsigned c_bucket[NSLOT];         // per-slot value bucket or INVALID
__device__ unsigned g_hist[NB];              // per-bucket peak count (zeroed by scatter)
__device__ unsigned g_off[NB];               // within-chunk "strictly-after" offsets
__device__ unsigned b_chunk[NCH];
__device__ unsigned b_csuf[NCH];
__device__ unsigned g_done;                  // scan ticket (reset by last block)
__device__ unsigned g_total;                 // min(raw, KPK)
__device__ unsigned g_tot_raw;
__device__ unsigned g_sorted_idx[KPK];

#define INVALID_B 0xFFFFFFFFu

__device__ __forceinline__ unsigned cell_of(unsigned idx) {
    unsigned z = idx >> 18, y = (idx >> 9) & 511u, x = idx & 511u;
    return ((z >> 3) << 12) | ((y >> 3) << 6) | (x >> 3);
}

// ---------------- kernel 1: stream volume, bin candidates into cell slots ------
__global__ void k_detect(const float* __restrict__ vol) {
    const float4* v4 = (const float4*)vol;
    unsigned tile = blockIdx.x * 2048u;
#pragma unroll
    for (int j = 0; j < 8; j++) {
        unsigned i = tile + j * 256u + threadIdx.x;
        float4 f = v4[i];
        unsigned base = i * 4u;
        float vv[4] = {f.x, f.y, f.z, f.w};
#pragma unroll
        for (int e = 0; e < 4; e++) {
            if (vv[e] > THRESH) {
                unsigned idx = base + (unsigned)e;
                unsigned c = cell_of(idx);
                unsigned slot = atomicAdd(&c_cnt[c], 1u);   // 65536 addrs: no contention
                if (slot < CSLOTS)
                    c_data[c * CSLOTS + slot] = make_uint2(idx, __float_as_uint(vv[e]));
            }
        }
    }
}

// ---------------- kernel 2: verify 7^3 local max via cell slots ----------------
// A defeating neighbor (> v > 0.997) is itself a candidate, so only candidate
// records in the <=8 overlapping cells need checking.
__global__ void k_verify() {
    unsigned i = blockIdx.x * blockDim.x + threadIdx.x;   // one thread per (cell,slot)
    unsigned cell = i >> 4, slot = i & 15u;
    unsigned cn = min(c_cnt[cell], (unsigned)CSLOTS);
    if (slot >= cn) return;
    uint2 me = c_data[i];
    unsigned idx = me.x;
    float v = __uint_as_float(me.y);
    int z = idx >> 18, y = (idx >> 9) & 511, x = idx & 511;

    int cz0 = max(z - 3, 0) >> 3, cz1 = min(z + 3, DD - 1) >> 3;
    int cy0 = max(y - 3, 0) >> 3, cy1 = min(y + 3, HH - 1) >> 3;
    int cx0 = max(x - 3, 0) >> 3, cx1 = min(x + 3, WW - 1) >> 3;
    bool peak = true;
    for (int cz = cz0; cz <= cz1 && peak; cz++)
    for (int cy = cy0; cy <= cy1 && peak; cy++)
    for (int cx = cx0; cx <= cx1 && peak; cx++) {
        unsigned c2 = ((unsigned)cz << 12) | ((unsigned)cy << 6) | (unsigned)cx;
        unsigned cn2 = min(c_cnt[c2], (unsigned)CSLOTS);
        unsigned b2 = c2 * CSLOTS;
        for (unsigned j = 0; j < cn2; j++) {
            uint2 r = c_data[b2 + j];
            if (__uint_as_float(r.y) > v) {
                int rz = r.x >> 18, ry = (r.x >> 9) & 511, rx = r.x & 511;
                if (abs(rz - z) <= 3 && abs(ry - y) <= 3 && abs(rx - x) <= 3) {
                    peak = false; break;
                }
            }
        }
    }
    unsigned bucket = INVALID_B;
    if (peak) {
        bucket = me.y & 0xFFFFu;   // monotone key: all values in (0.997,1) share top bits 0x3F7F
        atomicAdd(&g_hist[bucket], 1u);
    }
    c_bucket[i] = bucket;
}

// ---------------- kernel 3: fused two-level suffix (descending) scan -----------
// 64 blocks x 256 threads; each block scans its 1024-bucket chunk, then the
// last-arriving block does the 64-entry level-2 scan and resets the ticket.
__global__ void k_scan() {
    __shared__ unsigned s_h[1024];
    __shared__ unsigned s_w[8];
    __shared__ unsigned s_last;
    int t = threadIdx.x;
    unsigned base = blockIdx.x * 1024u;
#pragma unroll
    for (int j = 0; j < 4; j++) s_h[j * 256 + t] = g_hist[base + j * 256 + t];
    __syncthreads();
    unsigned h0 = s_h[t*4+0], h1 = s_h[t*4+1], h2 = s_h[t*4+2], h3 = s_h[t*4+3];
    unsigned sum4 = h0 + h1 + h2 + h3;
    unsigned v = sum4;
    int lane = t & 31, w = t >> 5;
#pragma unroll
    for (int d = 1; d < 32; d <<= 1) {
        unsigned o = __shfl_down_sync(0xFFFFFFFFu, v, d);
        if (lane + d < 32) v += o;
    }
    if (lane == 0) s_w[w] = v;
    __syncthreads();
    unsigned wafter = 0;
    for (int i = w + 1; i < 8; i++) wafter += s_w[i];
    unsigned run = wafter + (v - sum4);          // strictly-after, within chunk
    unsigned o3 = run; run += h3;
    unsigned o2 = run; run += h2;
    unsigned o1 = run; run += h1;
    unsigned o0 = run; run += h0;
    g_off[base + t*4 + 0] = o0;
    g_off[base + t*4 + 1] = o1;
    g_off[base + t*4 + 2] = o2;
    g_off[base + t*4 + 3] = o3;
    if (t == 0) b_chunk[blockIdx.x] = run;       // chunk total

    // ticket: last block performs level-2
    if (t == 0) {
        __threadfence();
        s_last = (atomicAdd(&g_done, 1u) == NCH - 1u) ? 1u : 0u;
    }
    __syncthreads();
    if (s_last) {
        volatile unsigned* vc = (volatile unsigned*)b_chunk;
        if (t < NCH) {
            unsigned suf = 0;
            for (int i = t + 1; i < NCH; i++) suf += vc[i];
            b_csuf[t] = suf;
            if (t == 0) {
                unsigned tot = suf + vc[0];
                g_tot_raw = tot;
                g_total = min(tot, (unsigned)KPK);
                g_done = 0u;                     // reset ticket for next replay
            }
        }
    }
}

// ---------------- kernel 4: scatter peaks into descending-value order ----------
// Position via atomicAdd(-1): also restores g_hist to all-zeros for next replay.
__global__ void k_scatter() {
    unsigned i = blockIdx.x * blockDim.x + threadIdx.x;
    unsigned cell = i >> 4, slot = i & 15u;
    unsigned cn = min(c_cnt[cell], (unsigned)CSLOTS);
    if (slot >= cn) return;
    unsigned b = c_bucket[i];
    if (b == INVALID_B) return;
    unsigned old = atomicAdd(&g_hist[b], 0xFFFFFFFFu);    // returns cnt..1; ends at 0
    unsigned pos = g_off[b] + b_csuf[b >> 10] + old - 1u;
    if (pos < (unsigned)KPK) g_sorted_idx[pos] = c_data[i].x;
}

// ---------------- kernel 5: per-bucket index sort + counter cleanup ------------
// Bucket counts recovered from scan differences (g_hist is already zeroed).
__global__ void k_bucket_sort() {
    unsigned b = blockIdx.x * blockDim.x + threadIdx.x;
    if (b >= NB) return;
    c_cnt[b] = 0u;                               // restore cell counters for next replay
    unsigned F = g_off[b] + b_csuf[b >> 10];
    unsigned Fprev = (b == 0u) ? g_tot_raw : (g_off[b - 1] + b_csuf[(b - 1) >> 10]);
    unsigned c = Fprev - F;
    if (c < 2u) return;
    if (F >= (unsigned)KPK) return;
    if (F + c > (unsigned)KPK) c = (unsigned)KPK - F;
    for (unsigned i = 1; i < c; i++) {
        unsigned key = g_sorted_idx[F + i];
        int j = (int)i - 1;
        while (j >= 0 && g_sorted_idx[F + j] > key) {
            g_sorted_idx[F + j + 1] = g_sorted_idx[F + j];
            j--;
        }
        g_sorted_idx[F + j + 1] = key;
    }
}

// ---------------- kernel 6: centroid refine + write output (1 warp per row) ----
// Vectorized: each 7-wide x-run covered by three aligned float4 loads from
// a = clamp((x-3)&~3, 0, 500); out-of-window elements weight-masked (matches
// the reference's zero padding).
__global__ void k_centroid(const float* __restrict__ vol, float* __restrict__ out,
                           float* __restrict__ validOut, int writeValid) {
    unsigned gtid = blockIdx.x * blockDim.x + threadIdx.x;
    unsigned row = gtid >> 5;
    int lane = threadIdx.x & 31;
    if (row >= (unsigned)KPK) return;
    unsigned total = g_total;
    if (row >= total) {
        if (lane == 0) {
            ((float4*)out)[row] = make_float4(0.f, 0.f, 0.f, 0.f);
            if (writeValid) validOut[row] = 0.f;
        }
        return;
    }
    unsigned idx = g_sorted_idx[row];
    int z = idx >> 18, y = (idx >> 9) & 511, x = idx & 511;

    int a = max(x - 3, 0) & ~3;
    if (a > WW - 12) a = WW - 12;

    float s0 = 0.f, sx = 0.f, sy = 0.f, sz = 0.f;
    for (int q = lane; q < 49; q += 32) {
        int dz = q / 7, dy = q - dz * 7;
        int zz = z + dz - 3, yy = y + dy - 3;
        if ((unsigned)zz < (unsigned)DD && (unsigned)yy < (unsigned)HH) {
            const float* rp = vol + ((unsigned)zz << 18) + ((unsigned)yy << 9);
            float4 A = *(const float4*)(rp + a);
            float4 B = *(const float4*)(rp + a + 4);
            float4 C = *(const float4*)(rp + a + 8);
            float vals[12] = {A.x, A.y, A.z, A.w, B.x, B.y, B.z, B.w, C.x, C.y, C.z, C.w};
            float rs0 = 0.f, rsx = 0.f;
#pragma unroll
            for (int e = 0; e < 12; e++) {
                int dx = a + e - x;
                bool in = (dx >= -3) && (dx <= 3);
                float vv = in ? vals[e] : 0.f;
                rs0 += vv;
                rsx += vv * (float)dx;
            }
            s0 += rs0;
            sx += rsx;
            sy += rs0 * (float)(dy - 3);
            sz += rs0 * (float)(dz - 3);
        }
    }
#pragma unroll
    for (int o = 16; o; o >>= 1) {
        s0 += __shfl_xor_sync(0xFFFFFFFFu, s0, o);
        sx += __shfl_xor_sync(0xFFFFFFFFu, sx, o);
        sy += __shfl_xor_sync(0xFFFFFFFFu, sy, o);
        sz += __shfl_xor_sync(0xFFFFFFFFu, sz, o);
    }
    if (lane == 0) {
        float val  = vol[idx];
        float inv  = 1.f / s0;
        float xrec = ((float)x + sx * inv - 255.5f) * 0.1f;
        float yrec = ((float)y + sy * inv - 255.5f) * 0.1f;
        float zrec = ((float)z + sz * inv + 0.5f) * 0.02f - 2.0f;
        ((float4*)out)[row] = make_float4(xrec, yrec, zrec, val);
        if (writeValid) validOut[row] = 1.f;
    }
}

// ---------------- launch (6 kernels) ----------------
extern "C" void kernel_launch(void* const* d_in, const int* in_sizes, int n_in,
                              void* d_out, int out_size) {
    const float* vol = (const float*)d_in[0];
    float* out = (float*)d_out;
    int writeValid = (out_size >= KPK * 5) ? 1 : 0;
    float* validOut = out + (size_t)KPK * 4;

    k_detect<<<4096, 256>>>(vol);
    k_verify<<<NSLOT / 256, 256>>>();
    k_scan<<<NCH, 256>>>();
    k_scatter<<<NSLOT / 256, 256>>>();
    k_bucket_sort<<<NB / 256, 256>>>();
    k_centroid<<<(KPK * 32) / 256, 256>>>(vol, out, validOut, writeValid);
}

// round 9
// speedup vs baseline: 1.1949x; 1.1949x over previous
#include <cuda_runtime.h>
#include <cuda_bf16.h>

#define DD 128
#define HH 512
#define WW 512
#define THRESH 0.997f
#define KPK 131072
#define NB  65536                 // value buckets AND spatial cells (16*64*64)
#define NCH 64                    // scan chunks of 1024 buckets
#define CSLOTS 16                 // per-cell candidate capacity (lambda~1.5 -> safe)
#define CAND_CAP (1<<18)          // 262144

// ------------- device scratch (static; all counters self-restore to 0) --------
__device__ unsigned c_cnt[NB];                // per-cell count   (zeroed by bucket_sort)
__device__ uint2    c_data[NB * CSLOTS];      // (idx, valbits) per cell slot
__device__ unsigned g_ncand;                  // compact count    (zeroed by bucket_sort)
__device__ uint2    g_cand[CAND_CAP];         // compact candidate list (idx, valbits)
__device__ unsigned g_cand_bucket[CAND_CAP];  // per-candidate bucket or INVALID
__device__ unsigned g_hist[NB];               // per-bucket peak count (zeroed by scatter)
__device__ unsigned g_off[NB];                // within-chunk strictly-after offsets
__device__ unsigned b_chunk[NCH];
__device__ unsigned b_csuf[NCH];
__device__ unsigned g_done;                   // scan ticket (reset by last block)
__device__ unsigned g_total;                  // min(raw, KPK)
__device__ unsigned g_tot_raw;
__device__ uint2    g_sorted[KPK];            // (idx, valbits) in final order

#define INVALID_B 0xFFFFFFFFu

__device__ __forceinline__ unsigned cell_of(unsigned idx) {
    unsigned z = idx >> 18, y = (idx >> 9) & 511u, x = idx & 511u;
    return ((z >> 3) << 12) | ((y >> 3) << 6) | (x >> 3);
}

// ---- kernel 1: stream volume; block-aggregated compact append + cell slots ----
__global__ void k_detect(const float* __restrict__ vol) {
    __shared__ uint2 s_cand[1024];
    __shared__ unsigned s_cnt, s_base;
    if (threadIdx.x == 0) s_cnt = 0u;
    __syncthreads();

    const float4* v4 = (const float4*)vol;
    unsigned tile = blockIdx.x * 2048u;
#pragma unroll
    for (int j = 0; j < 8; j++) {
        unsigned i = tile + j * 256u + threadIdx.x;
        float4 f = v4[i];
        unsigned base = i * 4u;
        float vv[4] = {f.x, f.y, f.z, f.w};
#pragma unroll
        for (int e = 0; e < 4; e++) {
            if (vv[e] > THRESH) {
                unsigned p = atomicAdd(&s_cnt, 1u);
                if (p < 1024u) s_cand[p] = make_uint2(base + (unsigned)e, __float_as_uint(vv[e]));
            }
        }
    }
    __syncthreads();
    unsigned cnt = min(s_cnt, 1024u);
    if (threadIdx.x == 0) s_base = atomicAdd(&g_ncand, cnt);
    __syncthreads();
    for (unsigned j = threadIdx.x; j < cnt; j += blockDim.x) {
        uint2 rec = s_cand[j];
        unsigned p = s_base + j;
        if (p < CAND_CAP) g_cand[p] = rec;
        unsigned c = cell_of(rec.x);
        unsigned slot = atomicAdd(&c_cnt[c], 1u);   // 65536 addrs: no contention
        if (slot < CSLOTS) c_data[c * CSLOTS + slot] = rec;
    }
}

// ---- kernel 2: verify 7^3 local max via cell probes (compact iteration) -------
// A defeating neighbor (> v > 0.997) is itself a candidate, so only candidate
// records in the <=8 overlapping cells need checking.
__global__ void k_verify() {
    unsigned i = blockIdx.x * blockDim.x + threadIdx.x;
    unsigned n = min(g_ncand, (unsigned)CAND_CAP);
    if (i >= n) return;
    uint2 me = g_cand[i];
    unsigned idx = me.x;
    float v = __uint_as_float(me.y);
    int z = idx >> 18, y = (idx >> 9) & 511, x = idx & 511;

    int cz0 = max(z - 3, 0) >> 3, cz1 = min(z + 3, DD - 1) >> 3;
    int cy0 = max(y - 3, 0) >> 3, cy1 = min(y + 3, HH - 1) >> 3;
    int cx0 = max(x - 3, 0) >> 3, cx1 = min(x + 3, WW - 1) >> 3;
    bool peak = true;
    for (int cz = cz0; cz <= cz1 && peak; cz++)
    for (int cy = cy0; cy <= cy1 && peak; cy++)
    for (int cx = cx0; cx <= cx1 && peak; cx++) {
        unsigned c2 = ((unsigned)cz << 12) | ((unsigned)cy << 6) | (unsigned)cx;
        unsigned cn2 = min(c_cnt[c2], (unsigned)CSLOTS);
        unsigned b2 = c2 * CSLOTS;
        for (unsigned j = 0; j < cn2; j++) {
            uint2 r = c_data[b2 + j];
            if (__uint_as_float(r.y) > v) {
                int rz = r.x >> 18, ry = (r.x >> 9) & 511, rx = r.x & 511;
                if (abs(rz - z) <= 3 && abs(ry - y) <= 3 && abs(rx - x) <= 3) {
                    peak = false; break;
                }
            }
        }
    }
    unsigned bucket = INVALID_B;
    if (peak) {
        bucket = me.y & 0xFFFFu;   // monotone key: all peaks share top bits 0x3F7F
        atomicAdd(&g_hist[bucket], 1u);
    }
    g_cand_bucket[i] = bucket;
}

// ---- kernel 3: fused two-level suffix (descending) scan over 65536 buckets ----
__global__ void k_scan() {
    __shared__ unsigned s_h[1024];
    __shared__ unsigned s_w[8];
    __shared__ unsigned s_last;
    int t = threadIdx.x;
    unsigned base = blockIdx.x * 1024u;
#pragma unroll
    for (int j = 0; j < 4; j++) s_h[j * 256 + t] = g_hist[base + j * 256 + t];
    __syncthreads();
    unsigned h0 = s_h[t*4+0], h1 = s_h[t*4+1], h2 = s_h[t*4+2], h3 = s_h[t*4+3];
    unsigned sum4 = h0 + h1 + h2 + h3;
    unsigned v = sum4;
    int lane = t & 31, w = t >> 5;
#pragma unroll
    for (int d = 1; d < 32; d <<= 1) {
        unsigned o = __shfl_down_sync(0xFFFFFFFFu, v, d);
        if (lane + d < 32) v += o;
    }
    if (lane == 0) s_w[w] = v;
    __syncthreads();
    unsigned wafter = 0;
    for (int i = w + 1; i < 8; i++) wafter += s_w[i];
    unsigned run = wafter + (v - sum4);          // strictly-after, within chunk
    unsigned o3 = run; run += h3;
    unsigned o2 = run; run += h2;
    unsigned o1 = run; run += h1;
    unsigned o0 = run; run += h0;
    g_off[base + t*4 + 0] = o0;
    g_off[base + t*4 + 1] = o1;
    g_off[base + t*4 + 2] = o2;
    g_off[base + t*4 + 3] = o3;
    if (t == 0) b_chunk[blockIdx.x] = run;       // chunk total

    if (t == 0) {
        __threadfence();
        s_last = (atomicAdd(&g_done, 1u) == NCH - 1u) ? 1u : 0u;
    }
    __syncthreads();
    if (s_last) {
        volatile unsigned* vc = (volatile unsigned*)b_chunk;
        if (t < NCH) {
            unsigned suf = 0;
            for (int i = t + 1; i < NCH; i++) suf += vc[i];
            b_csuf[t] = suf;
            if (t == 0) {
                unsigned tot = suf + vc[0];
                g_tot_raw = tot;
                g_total = min(tot, (unsigned)KPK);
                g_done = 0u;                     // reset ticket for next replay
            }
        }
    }
}

// ---- kernel 4: scatter peaks into descending-value order ----------------------
// Position via atomicAdd(-1): restores g_hist to all-zeros as a side effect.
__global__ void k_scatter() {
    unsigned i = blockIdx.x * blockDim.x + threadIdx.x;
    unsigned n = min(g_ncand, (unsigned)CAND_CAP);
    if (i >= n) return;
    unsigned b = g_cand_bucket[i];
    if (b == INVALID_B) return;
    unsigned old = atomicAdd(&g_hist[b], 0xFFFFFFFFu);    // returns cnt..1; ends at 0
    unsigned pos = g_off[b] + b_csuf[b >> 10] + old - 1u;
    if (pos < (unsigned)KPK) g_sorted[pos] = g_cand[i];
}

// ---- kernel 5: per-bucket index sort (ties: lower index first) + cleanup ------
__global__ void k_bucket_sort() {
    unsigned b = blockIdx.x * blockDim.x + threadIdx.x;
    if (b >= NB) return;
    c_cnt[b] = 0u;                               // restore cell counters
    if (b == 0u) g_ncand = 0u;                   // restore compact counter
    unsigned F = g_off[b] + b_csuf[b >> 10];
    unsigned Fprev = (b == 0u) ? g_tot_raw : (g_off[b - 1] + b_csuf[(b - 1) >> 10]);
    unsigned c = Fprev - F;                      // bucket count recovered from scan
    if (c < 2u) return;
    if (F >= (unsigned)KPK) return;
    if (F + c > (unsigned)KPK) c = (unsigned)KPK - F;
    for (unsigned i = 1; i < c; i++) {
        uint2 key = g_sorted[F + i];
        int j = (int)i - 1;
        while (j >= 0 && g_sorted[F + j].x > key.x) {
            g_sorted[F + j + 1] = g_sorted[F + j];
            j--;
        }
        g_sorted[F + j + 1] = key;
    }
}

// ---- kernel 6: centroid refine + write output (1 warp per row) ----------------
// Each 7-wide x-run covered by three aligned float4 loads from
// a = clamp((x-3)&~3, 0, 500); out-of-window elements weight-masked (matches
// the reference's zero padding). Peak value comes from the sorted record.
__global__ void k_centroid(const float* __restrict__ vol, float* __restrict__ out,
                           float* __restrict__ validOut, int writeValid) {
    unsigned gtid = blockIdx.x * blockDim.x + threadIdx.x;
    unsigned row = gtid >> 5;
    int lane = threadIdx.x & 31;
    if (row >= (unsigned)KPK) return;
    unsigned total = g_total;
    if (row >= total) {
        if (lane == 0) {
            ((float4*)out)[row] = make_float4(0.f, 0.f, 0.f, 0.f);
            if (writeValid) validOut[row] = 0.f;
        }
        return;
    }
    uint2 rec = g_sorted[row];
    unsigned idx = rec.x;
    int z = idx >> 18, y = (idx >> 9) & 511, x = idx & 511;

    int a = max(x - 3, 0) & ~3;
    if (a > WW - 12) a = WW - 12;

    float s0 = 0.f, sx = 0.f, sy = 0.f, sz = 0.f;
    for (int q = lane; q < 49; q += 32) {
        int dz = q / 7, dy = q - dz * 7;
        int zz = z + dz - 3, yy = y + dy - 3;
        if ((unsigned)zz < (unsigned)DD && (unsigned)yy < (unsigned)HH) {
            const float* rp = vol + ((unsigned)zz << 18) + ((unsigned)yy << 9);
            float4 A = *(const float4*)(rp + a);
            float4 B = *(const float4*)(rp + a + 4);
            float4 C = *(const float4*)(rp + a + 8);
            float vals[12] = {A.x, A.y, A.z, A.w, B.x, B.y, B.z, B.w, C.x, C.y, C.z, C.w};
            float rs0 = 0.f, rsx = 0.f;
#pragma unroll
            for (int e = 0; e < 12; e++) {
                int dx = a + e - x;
                bool in = (dx >= -3) && (dx <= 3);
                float vv = in ? vals[e] : 0.f;
                rs0 += vv;
                rsx += vv * (float)dx;
            }
            s0 += rs0;
            sx += rsx;
            sy += rs0 * (float)(dy - 3);
            sz += rs0 * (float)(dz - 3);
        }
    }
#pragma unroll
    for (int o = 16; o; o >>= 1) {
        s0 += __shfl_xor_sync(0xFFFFFFFFu, s0, o);
        sx += __shfl_xor_sync(0xFFFFFFFFu, sx, o);
        sy += __shfl_xor_sync(0xFFFFFFFFu, sy, o);
        sz += __shfl_xor_sync(0xFFFFFFFFu, sz, o);
    }
    if (lane == 0) {
        float val  = __uint_as_float(rec.y);
        float inv  = 1.f / s0;
        float xrec = ((float)x + sx * inv - 255.5f) * 0.1f;
        float yrec = ((float)y + sy * inv - 255.5f) * 0.1f;
        float zrec = ((float)z + sz * inv + 0.5f) * 0.02f - 2.0f;
        ((float4*)out)[row] = make_float4(xrec, yrec, zrec, val);
        if (writeValid) validOut[row] = 1.f;
    }
}

// ---------------- launch (6 kernels) ----------------
extern "C" void kernel_launch(void* const* d_in, const int* in_sizes, int n_in,
                              void* d_out, int out_size) {
    const float* vol = (const float*)d_in[0];
    float* out = (float*)d_out;
    int writeValid = (out_size >= KPK * 5) ? 1 : 0;
    float* validOut = out + (size_t)KPK * 4;

    k_detect<<<4096, 256>>>(vol);
    k_verify<<<CAND_CAP / 256, 256>>>();
    k_scan<<<NCH, 256>>>();
    k_scatter<<<CAND_CAP / 256, 256>>>();
    k_bucket_sort<<<NB / 256, 256>>>();
    k_centroid<<<(KPK * 32) / 256, 256>>>(vol, out, validOut, writeValid);
}